// round 13
// baseline (speedup 1.0000x reference)
#include <cuda_runtime.h>

// FDTD 2-step update (Ampere + Faraday, 3rd-order one-sided boundary stencils)
// B=8, E:1024x1024, Hx:1022x1023, Hy:1023x1022.
// Outputs concat axis 1: E:(8,2048,1024)  Hx:(8,2044,1023)  Hy:(8,2046,1022)
// DT/DX = DT/(Z*DY) = 0.5 ; cf = [-11/6, 3, -3/2, 1/3]

#define CF0 (-11.0f/6.0f)
#define CF1 ( 3.0f)
#define CF2 (-1.5f)
#define CF3 ( 1.0f/3.0f)

// Combined (fwd+bwd) stencil coefficients, 0.5 folded in.
#define W8_INIT  { -0.5f*CF3, -0.5f*CF2, -0.5f*CF1, -0.5f*CF0, 0.5f*CF0, 0.5f*CF1, 0.5f*CF2, 0.5f*CF3 }
#define HW8_INIT {  0.5f*CF3,  0.5f*CF2,  0.5f*CF1,  0.5f*CF0,-0.5f*CF0,-0.5f*CF1,-0.5f*CF2,-0.5f*CF3 }
#define FX6_INIT { -0.5f*CF3, -0.5f*CF2, 0.5f*(CF0-CF1), 0.5f*(CF1-CF0), 0.5f*CF2, 0.5f*CF3 }

// ===========================================================================
// Per-point slow-path (boundary) functions — identical math to passing code
// ===========================================================================
__device__ __forceinline__ float amper_pt_slow(
    const float* __restrict__ E, const float* __restrict__ Hx,
    const float* __restrict__ Hy, const float fl[12], int i, int j)
{
    float s = __ldg(E + i*1024 + j);
    if (i >= 2 && i <= 1021 && j >= 2 && j <= 1021) {
        float a1 = 0.f;
        #pragma unroll
        for (int a = 0; a < 4; a++)
            #pragma unroll
            for (int b = 0; b < 3; b++)
                a1 = fmaf(__ldg(Hy + (i-2+a)*1022 + (j-2+b)), fl[b*4+a], a1);
        float a2 = 0.f;
        #pragma unroll
        for (int a = 0; a < 3; a++)
            #pragma unroll
            for (int b = 0; b < 4; b++)
                a2 = fmaf(__ldg(Hx + (i-2+a)*1023 + (j-2+b)), fl[a*4+b], a2);
        s += 0.5f * (a1 - a2);
    }
    if (i <= 1019 && j >= 1 && j <= 1022) {
        const float* p = Hy + i*1022 + (j-1);
        s += 0.5f*(CF0*__ldg(p) + CF1*__ldg(p+1022) + CF2*__ldg(p+2044) + CF3*__ldg(p+3066));
    }
    if (i >= 4 && j >= 1 && j <= 1022) {
        const float* p = Hy + (i-4)*1022 + (j-1);
        s -= 0.5f*(CF3*__ldg(p) + CF2*__ldg(p+1022) + CF1*__ldg(p+2044) + CF0*__ldg(p+3066));
    }
    if (i >= 1 && i <= 1022 && j <= 1019) {
        const float* p = Hx + (i-1)*1023 + j;
        s -= 0.5f*(CF0*__ldg(p) + CF1*__ldg(p+1) + CF2*__ldg(p+2) + CF3*__ldg(p+3));
    }
    if (i >= 1 && i <= 1022 && j >= 4) {
        const float* p = Hx + (i-1)*1023 + (j-4);
        s += 0.5f*(CF3*__ldg(p) + CF2*__ldg(p+1) + CF1*__ldg(p+2) + CF0*__ldg(p+3));
    }
    return s;
}

__device__ __forceinline__ float hx_pt_slow(
    const float* __restrict__ E, const float* __restrict__ Hx,
    const float fl[12], int i, int j)
{
    float s3 = 0.f;
    if (j >= 1 && j <= 1021) {
        float a = 0.f;
        #pragma unroll
        for (int a2 = 0; a2 < 3; a2++)
            #pragma unroll
            for (int b = 0; b < 4; b++)
                a = fmaf(__ldg(E + (i+a2)*1024 + (j-1+b)), fl[a2*4+b], a);
        s3 += 0.5f * a;
    }
    if (j <= 1020) {
        const float* p = E + (i+1)*1024 + j;
        s3 += 0.5f*(CF0*__ldg(p) + CF1*__ldg(p+1) + CF2*__ldg(p+2) + CF3*__ldg(p+3));
    }
    if (j >= 2) {
        const float* p = E + (i+1)*1024 + (j-2);
        s3 -= 0.5f*(CF3*__ldg(p) + CF2*__ldg(p+1) + CF1*__ldg(p+2) + CF0*__ldg(p+3));
    }
    return __ldg(Hx + i*1023 + j) - s3;
}

__device__ __forceinline__ float hy_pt_slow(
    const float* __restrict__ E, const float* __restrict__ Hy,
    const float fl[12], int i, int j)
{
    float s4 = 0.f;
    if (i >= 1 && i <= 1021) {
        float a = 0.f;
        #pragma unroll
        for (int a2 = 0; a2 < 4; a2++)
            #pragma unroll
            for (int b = 0; b < 3; b++)
                a = fmaf(__ldg(E + (i-1+a2)*1024 + (j+b)), fl[b*4+a2], a);
        s4 += 0.5f * a;
    }
    if (i <= 1020) {
        const float* p = E + i*1024 + (j+1);
        s4 += 0.5f*(CF0*__ldg(p) + CF1*__ldg(p+1024) + CF2*__ldg(p+2048) + CF3*__ldg(p+3072));
    }
    if (i >= 2) {
        const float* p = E + (i-2)*1024 + (j+1);
        s4 -= 0.5f*(CF3*__ldg(p) + CF2*__ldg(p+1024) + CF1*__ldg(p+2048) + CF0*__ldg(p+3072));
    }
    return __ldg(Hy + i*1022 + j) + s4;
}

// ===========================================================================
// Ampere: block tile = 64 rows x 32 cols; thread = 8 rows x 1 col.
// Smem: Hy rows [bi0-4, bi0+66], cols [bj0-2, bj0+32]  (71 x 35, stride 36)
//       Hx rows [bi0-2, bi0+63], cols [bj0-4, bj0+34]  (66 x 39, stride 40)
// ===========================================================================
__global__ __launch_bounds__(256)
void amper_kernel(const float* __restrict__ E,  int Es,
                  const float* __restrict__ Hx, int Hxs,
                  const float* __restrict__ Hy, int Hys,
                  const float* __restrict__ F,
                  float* __restrict__ Eout, int Eos)
{
    __shared__ float HyS[71 * 36];
    __shared__ float HxS[66 * 40];

    const int b = blockIdx.z;
    E    += (size_t)b * Es;
    Hx   += (size_t)b * Hxs;
    Hy   += (size_t)b * Hys;
    Eout += (size_t)b * Eos;

    float fl05[12], fl[12];
    #pragma unroll
    for (int k = 0; k < 12; k++) { fl[k] = __ldg(F + k); fl05[k] = 0.5f * fl[k]; }

    const int bj0 = blockIdx.x * 32;
    const int bi0 = blockIdx.y * 64;
    const int tx  = threadIdx.x;
    const int ty  = threadIdx.y;

    // ---- stage Hy ----
    for (int r = ty; r < 71; r += 8) {
        const int gr = bi0 - 4 + r;
        const bool rok = (gr >= 0 && gr < 1023);
        #pragma unroll
        for (int c = tx; c < 35; c += 32) {
            const int gc = bj0 - 2 + c;
            HyS[r*36 + c] = (rok && gc >= 0 && gc < 1022) ? __ldg(Hy + gr*1022 + gc) : 0.f;
        }
    }
    // ---- stage Hx ----
    for (int r = ty; r < 66; r += 8) {
        const int gr = bi0 - 2 + r;
        const bool rok = (gr >= 0 && gr < 1022);
        #pragma unroll
        for (int c = tx; c < 39; c += 32) {
            const int gc = bj0 - 4 + c;
            HxS[r*40 + c] = (rok && gc >= 0 && gc < 1023) ? __ldg(Hx + gr*1023 + gc) : 0.f;
        }
    }
    __syncthreads();

    const float W8[8]  = W8_INIT;
    const float HW8[8] = HW8_INIT;

    const int j   = bj0 + tx;
    const int ri0 = ty * 8;
    const int i0  = bi0 + ri0;
    const bool jfast = (j >= 4 && j <= 1019);

    #pragma unroll
    for (int d = 0; d < 8; ++d) {
        const int i = i0 + d, ri = ri0 + d;
        float v;
        if (jfast && i >= 4 && i <= 1019) {
            float s = __ldg(E + i*1024 + j);
            // combined vertical 8-tap (Hy), col j-1, rows i-4..i+3
            #pragma unroll
            for (int o = 0; o < 8; ++o)
                s = fmaf(W8[o], HyS[(ri+o)*36 + tx+1], s);
            // conv(Hy, f^T), rows i-2..i+1, cols j-2..j (added)
            #pragma unroll
            for (int a = 0; a < 4; ++a)
                #pragma unroll
                for (int bb = 0; bb < 3; ++bb)
                    s = fmaf(fl05[bb*4+a], HyS[(ri+2+a)*36 + tx+bb], s);
            // combined horizontal 8-tap (Hx), row i-1, cols j-4..j+3
            #pragma unroll
            for (int o = 0; o < 8; ++o)
                s = fmaf(HW8[o], HxS[(ri+1)*40 + tx+o], s);
            // conv(Hx, f), rows i-2..i, cols j-2..j+1 (subtracted)
            #pragma unroll
            for (int a = 0; a < 3; ++a)
                #pragma unroll
                for (int bb = 0; bb < 4; ++bb)
                    s = fmaf(-fl05[a*4+bb], HxS[(ri+a)*40 + tx+2+bb], s);
            v = s;
        } else {
            v = amper_pt_slow(E, Hx, Hy, fl, i, j);
        }
        Eout[i*1024 + j] = v;
    }
}

// ===========================================================================
// Faraday: block tile = 64 rows x 32 cols; thread = 8 rows x 1 col.
// Smem: E rows [bi0-2, bi0+66], cols [bj0-2, bj0+34]  (69 x 37, stride 40)
// ===========================================================================
__global__ __launch_bounds__(256)
void faraday_kernel(const float* __restrict__ E,  int Es,
                    const float* __restrict__ Hx, int Hxs,
                    const float* __restrict__ Hy, int Hys,
                    const float* __restrict__ F,
                    float* __restrict__ Hxout, int Hxos,
                    float* __restrict__ Hyout, int Hyos)
{
    __shared__ float ES[69 * 40];

    const int b = blockIdx.z;
    E     += (size_t)b * Es;
    Hx    += (size_t)b * Hxs;
    Hy    += (size_t)b * Hys;
    Hxout += (size_t)b * Hxos;
    Hyout += (size_t)b * Hyos;

    float fl05[12], fl[12];
    #pragma unroll
    for (int k = 0; k < 12; k++) { fl[k] = __ldg(F + k); fl05[k] = 0.5f * fl[k]; }

    const int bj0 = blockIdx.x * 32;
    const int bi0 = blockIdx.y * 64;
    const int tx  = threadIdx.x;
    const int ty  = threadIdx.y;

    // ---- stage E ----
    for (int r = ty; r < 69; r += 8) {
        const int gr = bi0 - 2 + r;
        const bool rok = (gr >= 0 && gr < 1024);
        #pragma unroll
        for (int c = tx; c < 37; c += 32) {
            const int gc = bj0 - 2 + c;
            ES[r*40 + c] = (rok && gc >= 0 && gc < 1024) ? __ldg(E + gr*1024 + gc) : 0.f;
        }
    }
    __syncthreads();

    const float FX6[6] = FX6_INIT;

    const int j   = bj0 + tx;
    const int ri0 = ty * 8;
    const int i0  = bi0 + ri0;
    const bool jx_fast = (j >= 2 && j <= 1020);

    // ---- Hx_n ----
    if (j < 1023) {
        #pragma unroll
        for (int d = 0; d < 8; ++d) {
            const int i = i0 + d, ri = ri0 + d;
            if (i >= 1022) break;
            float v;
            if (jx_fast) {
                float s = __ldg(Hx + i*1023 + j);
                // combined 6-tap on row i+1, cols j-2..j+3 (subtracted)
                #pragma unroll
                for (int o = 0; o < 6; ++o)
                    s = fmaf(-FX6[o], ES[(ri+3)*40 + tx+o], s);
                // conv(E, f): rows i..i+2, cols j-1..j+2 (subtracted)
                #pragma unroll
                for (int a = 0; a < 3; ++a)
                    #pragma unroll
                    for (int bb = 0; bb < 4; ++bb)
                        s = fmaf(-fl05[a*4+bb], ES[(ri+2+a)*40 + tx+1+bb], s);
                v = s;
            } else {
                v = hx_pt_slow(E, Hx, fl, i, j);
            }
            Hxout[i*1023 + j] = v;
        }
    }

    // ---- Hy_n ----
    if (j < 1022) {
        #pragma unroll
        for (int d = 0; d < 8; ++d) {
            const int i = i0 + d, ri = ri0 + d;
            if (i >= 1023) break;
            float v;
            if (i >= 2 && i <= 1020) {
                float s = __ldg(Hy + i*1022 + j);
                // combined 6-tap on col j+1, rows i-2..i+3 (added)
                #pragma unroll
                for (int o = 0; o < 6; ++o)
                    s = fmaf(FX6[o], ES[(ri+o)*40 + tx+3], s);
                // conv(E, f^T): rows i-1..i+2, cols j..j+2 (added)
                #pragma unroll
                for (int a = 0; a < 4; ++a)
                    #pragma unroll
                    for (int bb = 0; bb < 3; ++bb)
                        s = fmaf(fl05[bb*4+a], ES[(ri+1+a)*40 + tx+2+bb], s);
                v = s;
            } else {
                v = hy_pt_slow(E, Hy, fl, i, j);
            }
            Hyout[i*1022 + j] = v;
        }
    }
}

// ---------------------------------------------------------------------------
// Launch: 4 passes; intermediates (E_n, Hx_n, Hy_n) live directly in d_out.
// ---------------------------------------------------------------------------
extern "C" void kernel_launch(void* const* d_in, const int* in_sizes, int n_in,
                              void* d_out, int out_size)
{
    const float* E  = (const float*)d_in[0];   // (8,1024,1024,1)
    const float* Hx = (const float*)d_in[1];   // (8,1022,1023,1)
    const float* Hy = (const float*)d_in[2];   // (8,1023,1022,1)
    const float* F  = (const float*)d_in[3];   // (3,4,1,1)

    float* out   = (float*)d_out;
    const int B  = 8;
    float* outE  = out;                                   // 8 * 2048*1024
    float* outHx = outE  + (size_t)B * 2048 * 1024;       // 8 * 2044*1023
    float* outHy = outHx + (size_t)B * 2044 * 1023;       // 8 * 2046*1022

    const int Es   = 1024*1024, Hxs  = 1022*1023, Hys  = 1023*1022;
    const int Eos  = 2048*1024, Hxos = 2044*1023, Hyos = 2046*1022;

    dim3 blk(32, 8, 1);
    dim3 grd(32, 16, B);   // 32-col x 64-row tiles over 1024x1024

    // Step 1
    amper_kernel<<<grd, blk>>>(E, Es, Hx, Hxs, Hy, Hys, F, outE, Eos);
    faraday_kernel<<<grd, blk>>>(outE, Eos, Hx, Hxs, Hy, Hys, F,
                                 outHx, Hxos, outHy, Hyos);
    // Step 2 (reads step-1 results from d_out)
    amper_kernel<<<grd, blk>>>(outE, Eos, outHx, Hxos, outHy, Hyos, F,
                               outE + 1024*1024, Eos);
    faraday_kernel<<<grd, blk>>>(outE + 1024*1024, Eos, outHx, Hxos, outHy, Hyos, F,
                                 outHx + 1022*1023, Hxos, outHy + 1023*1022, Hyos);
}

// round 16
// speedup vs baseline: 1.6109x; 1.6109x over previous
#include <cuda_runtime.h>

// FDTD 2-step update (Ampere + Faraday, 3rd-order one-sided boundary stencils)
// B=8, E:1024x1024, Hx:1022x1023, Hy:1023x1022.
// Outputs concat axis 1: E:(8,2048,1024)  Hx:(8,2044,1023)  Hy:(8,2046,1022)
// DT/DX = DT/(Z*DY) = 0.5 ; cf = [-11/6, 3, -3/2, 1/3]

#define CF0 (-11.0f/6.0f)
#define CF1 ( 3.0f)
#define CF2 (-1.5f)
#define CF3 ( 1.0f/3.0f)

// Combined (fwd+bwd) stencil coefficients, 0.5 folded in.
#define W8_INIT  { -0.5f*CF3, -0.5f*CF2, -0.5f*CF1, -0.5f*CF0, 0.5f*CF0, 0.5f*CF1, 0.5f*CF2, 0.5f*CF3 }
#define HW8_INIT {  0.5f*CF3,  0.5f*CF2,  0.5f*CF1,  0.5f*CF0,-0.5f*CF0,-0.5f*CF1,-0.5f*CF2,-0.5f*CF3 }
#define FX6_INIT { -0.5f*CF3, -0.5f*CF2, 0.5f*(CF0-CF1), 0.5f*(CF1-CF0), 0.5f*CF2, 0.5f*CF3 }

// ===========================================================================
// Per-point slow-path (boundary) functions — load F locally (not reg-resident
// in the fast path). Identical math to the passing kernels.
// ===========================================================================
__device__ __noinline__ float amper_pt_slow(
    const float* __restrict__ E, const float* __restrict__ Hx,
    const float* __restrict__ Hy, const float* __restrict__ F, int i, int j)
{
    float fl[12];
    #pragma unroll
    for (int k = 0; k < 12; k++) fl[k] = __ldg(F + k);

    float s = __ldg(E + i*1024 + j);
    if (i >= 2 && i <= 1021 && j >= 2 && j <= 1021) {
        float a1 = 0.f;
        #pragma unroll
        for (int a = 0; a < 4; a++)
            #pragma unroll
            for (int b = 0; b < 3; b++)
                a1 = fmaf(__ldg(Hy + (i-2+a)*1022 + (j-2+b)), fl[b*4+a], a1);
        float a2 = 0.f;
        #pragma unroll
        for (int a = 0; a < 3; a++)
            #pragma unroll
            for (int b = 0; b < 4; b++)
                a2 = fmaf(__ldg(Hx + (i-2+a)*1023 + (j-2+b)), fl[a*4+b], a2);
        s += 0.5f * (a1 - a2);
    }
    if (i <= 1019 && j >= 1 && j <= 1022) {
        const float* p = Hy + i*1022 + (j-1);
        s += 0.5f*(CF0*__ldg(p) + CF1*__ldg(p+1022) + CF2*__ldg(p+2044) + CF3*__ldg(p+3066));
    }
    if (i >= 4 && j >= 1 && j <= 1022) {
        const float* p = Hy + (i-4)*1022 + (j-1);
        s -= 0.5f*(CF3*__ldg(p) + CF2*__ldg(p+1022) + CF1*__ldg(p+2044) + CF0*__ldg(p+3066));
    }
    if (i >= 1 && i <= 1022 && j <= 1019) {
        const float* p = Hx + (i-1)*1023 + j;
        s -= 0.5f*(CF0*__ldg(p) + CF1*__ldg(p+1) + CF2*__ldg(p+2) + CF3*__ldg(p+3));
    }
    if (i >= 1 && i <= 1022 && j >= 4) {
        const float* p = Hx + (i-1)*1023 + (j-4);
        s += 0.5f*(CF3*__ldg(p) + CF2*__ldg(p+1) + CF1*__ldg(p+2) + CF0*__ldg(p+3));
    }
    return s;
}

__device__ __noinline__ float hx_pt_slow(
    const float* __restrict__ E, const float* __restrict__ Hx,
    const float* __restrict__ F, int i, int j)
{
    float fl[12];
    #pragma unroll
    for (int k = 0; k < 12; k++) fl[k] = __ldg(F + k);

    float s3 = 0.f;
    if (j >= 1 && j <= 1021) {
        float a = 0.f;
        #pragma unroll
        for (int a2 = 0; a2 < 3; a2++)
            #pragma unroll
            for (int b = 0; b < 4; b++)
                a = fmaf(__ldg(E + (i+a2)*1024 + (j-1+b)), fl[a2*4+b], a);
        s3 += 0.5f * a;
    }
    if (j <= 1020) {
        const float* p = E + (i+1)*1024 + j;
        s3 += 0.5f*(CF0*__ldg(p) + CF1*__ldg(p+1) + CF2*__ldg(p+2) + CF3*__ldg(p+3));
    }
    if (j >= 2) {
        const float* p = E + (i+1)*1024 + (j-2);
        s3 -= 0.5f*(CF3*__ldg(p) + CF2*__ldg(p+1) + CF1*__ldg(p+2) + CF0*__ldg(p+3));
    }
    return __ldg(Hx + i*1023 + j) - s3;
}

__device__ __noinline__ float hy_pt_slow(
    const float* __restrict__ E, const float* __restrict__ Hy,
    const float* __restrict__ F, int i, int j)
{
    float fl[12];
    #pragma unroll
    for (int k = 0; k < 12; k++) fl[k] = __ldg(F + k);

    float s4 = 0.f;
    if (i >= 1 && i <= 1021) {
        float a = 0.f;
        #pragma unroll
        for (int a2 = 0; a2 < 4; a2++)
            #pragma unroll
            for (int b = 0; b < 3; b++)
                a = fmaf(__ldg(E + (i-1+a2)*1024 + (j+b)), fl[b*4+a2], a);
        s4 += 0.5f * a;
    }
    if (i <= 1020) {
        const float* p = E + i*1024 + (j+1);
        s4 += 0.5f*(CF0*__ldg(p) + CF1*__ldg(p+1024) + CF2*__ldg(p+2048) + CF3*__ldg(p+3072));
    }
    if (i >= 2) {
        const float* p = E + (i-2)*1024 + (j+1);
        s4 -= 0.5f*(CF3*__ldg(p) + CF2*__ldg(p+1024) + CF1*__ldg(p+2048) + CF0*__ldg(p+3072));
    }
    return __ldg(Hy + i*1022 + j) + s4;
}

// ===========================================================================
// Ampere kernel: each thread computes a 4x4 tile of E_n (register streaming).
// ===========================================================================
__global__ __launch_bounds__(256, 5)
void amper_kernel(const float* __restrict__ E,  int Es,
                  const float* __restrict__ Hx, int Hxs,
                  const float* __restrict__ Hy, int Hys,
                  const float* __restrict__ F,
                  float* __restrict__ Eout, int Eos)
{
    const int b = blockIdx.z;
    E    += (size_t)b * Es;
    Hx   += (size_t)b * Hxs;
    Hy   += (size_t)b * Hys;
    Eout += (size_t)b * Eos;

    const int j0 = (blockIdx.x * 32 + threadIdx.x) * 4;   // 0..1020
    const int i0 = (blockIdx.y * 8  + threadIdx.y) * 4;   // 0..1020

    if (i0 >= 4 && i0 <= 1016 && j0 >= 4 && j0 <= 1016) {
        float fl05[12];
        #pragma unroll
        for (int k = 0; k < 12; k++) fl05[k] = 0.5f * __ldg(F + k);

        const float W8[8]  = W8_INIT;
        const float HW8[8] = HW8_INIT;

        float acc[4][4];
        #pragma unroll
        for (int li = 0; li < 4; ++li) {
            float4 e = *reinterpret_cast<const float4*>(E + (i0+li)*1024 + j0);
            acc[li][0]=e.x; acc[li][1]=e.y; acc[li][2]=e.z; acc[li][3]=e.w;
        }

        // ---- Hy phase: stream 11 rows (i0-4 .. i0+6), cols j0-2..j0+3 ----
        #pragma unroll
        for (int t = 0; t < 11; ++t) {
            const float* hb = Hy + (i0 - 4 + t)*1022 + (j0 - 2);
            float2 v0 = *reinterpret_cast<const float2*>(hb);
            float2 v1 = *reinterpret_cast<const float2*>(hb + 2);
            float2 v2 = *reinterpret_cast<const float2*>(hb + 4);
            float h[6] = { v0.x, v0.y, v1.x, v1.y, v2.x, v2.y };
            #pragma unroll
            for (int li = 0; li < 4; ++li) {
                const int o = t - li;          // combined 8-tap vertical, col j-1
                if (o >= 0 && o < 8) {
                    #pragma unroll
                    for (int c = 0; c < 4; ++c)
                        acc[li][c] = fmaf(W8[o], h[c+1], acc[li][c]);
                }
                const int a = t - 2 - li;      // conv(Hy, f^T), added
                if (a >= 0 && a < 4) {
                    #pragma unroll
                    for (int bb = 0; bb < 3; ++bb)
                        #pragma unroll
                        for (int c = 0; c < 4; ++c)
                            acc[li][c] = fmaf(fl05[bb*4 + a], h[c+bb], acc[li][c]);
                }
            }
        }

        // ---- Hx phase: stream 6 rows (i0-2 .. i0+3), cols j0-4..j0+6 ----
        #pragma unroll
        for (int t = 0; t < 6; ++t) {
            const float* xb = Hx + (i0 - 2 + t)*1023 + (j0 - 4);
            float x[11];
            #pragma unroll
            for (int k = 0; k < 11; ++k) x[k] = __ldg(xb + k);
            {
                const int li = t - 1;          // combined 8-tap horizontal, row i-1
                if (li >= 0 && li < 4) {
                    #pragma unroll
                    for (int c = 0; c < 4; ++c)
                        #pragma unroll
                        for (int o = 0; o < 8; ++o)
                            acc[li][c] = fmaf(HW8[o], x[c+o], acc[li][c]);
                }
            }
            #pragma unroll
            for (int li = 0; li < 4; ++li) {
                const int a = t - li;          // conv(Hx, f), subtracted
                if (a >= 0 && a < 3) {
                    #pragma unroll
                    for (int bb = 0; bb < 4; ++bb)
                        #pragma unroll
                        for (int c = 0; c < 4; ++c)
                            acc[li][c] = fmaf(-fl05[a*4 + bb], x[c+2+bb], acc[li][c]);
                }
            }
        }

        #pragma unroll
        for (int li = 0; li < 4; ++li)
            *reinterpret_cast<float4*>(Eout + (i0+li)*1024 + j0) =
                make_float4(acc[li][0], acc[li][1], acc[li][2], acc[li][3]);
    } else {
        #pragma unroll
        for (int li = 0; li < 4; ++li)
            for (int c = 0; c < 4; ++c)
                Eout[(i0+li)*1024 + j0 + c] = amper_pt_slow(E, Hx, Hy, F, i0+li, j0+c);
    }
}

// ===========================================================================
// Faraday kernel: each thread computes 4x4 tiles of Hx_n and Hy_n.
// ===========================================================================
__global__ __launch_bounds__(256, 5)
void faraday_kernel(const float* __restrict__ E,  int Es,
                    const float* __restrict__ Hx, int Hxs,
                    const float* __restrict__ Hy, int Hys,
                    const float* __restrict__ F,
                    float* __restrict__ Hxout, int Hxos,
                    float* __restrict__ Hyout, int Hyos)
{
    const int b = blockIdx.z;
    E     += (size_t)b * Es;
    Hx    += (size_t)b * Hxs;
    Hy    += (size_t)b * Hys;
    Hxout += (size_t)b * Hxos;
    Hyout += (size_t)b * Hyos;

    const int j0 = (blockIdx.x * 32 + threadIdx.x) * 4;   // 0..1020
    const int i0 = (blockIdx.y * 8  + threadIdx.y) * 4;   // 0..1020

    if (i0 >= 4 && i0 <= 1016 && j0 >= 4 && j0 <= 1016) {
        float fl05[12];
        #pragma unroll
        for (int k = 0; k < 12; k++) fl05[k] = 0.5f * __ldg(F + k);

        const float FX6[6] = FX6_INIT;

        // ---- Hx_n: stream E rows i0..i0+5, cols j0-4..j0+7 (3x float4) ----
        float ax[4][4];
        #pragma unroll
        for (int li = 0; li < 4; ++li)
            #pragma unroll
            for (int c = 0; c < 4; ++c)
                ax[li][c] = __ldg(Hx + (i0+li)*1023 + j0 + c);

        #pragma unroll
        for (int t = 0; t < 6; ++t) {
            const float* eb = E + (i0 + t)*1024 + (j0 - 4);
            float4 e0 = *reinterpret_cast<const float4*>(eb);
            float4 e1 = *reinterpret_cast<const float4*>(eb + 4);
            float4 e2 = *reinterpret_cast<const float4*>(eb + 8);
            float e[12] = { e0.x,e0.y,e0.z,e0.w, e1.x,e1.y,e1.z,e1.w, e2.x,e2.y,e2.z,e2.w };
            {
                const int li = t - 1;          // combined 6-tap horizontal on row i+1
                if (li >= 0 && li < 4) {
                    #pragma unroll
                    for (int c = 0; c < 4; ++c)
                        #pragma unroll
                        for (int o = 0; o < 6; ++o)
                            ax[li][c] = fmaf(-FX6[o], e[c+2+o], ax[li][c]);
                }
            }
            #pragma unroll
            for (int li = 0; li < 4; ++li) {
                const int a = t - li;          // conv(E, f), subtracted
                if (a >= 0 && a < 3) {
                    #pragma unroll
                    for (int bb = 0; bb < 4; ++bb)
                        #pragma unroll
                        for (int c = 0; c < 4; ++c)
                            ax[li][c] = fmaf(-fl05[a*4 + bb], e[c+3+bb], ax[li][c]);
                }
            }
        }
        #pragma unroll
        for (int li = 0; li < 4; ++li)
            #pragma unroll
            for (int c = 0; c < 4; ++c)
                Hxout[(i0+li)*1023 + j0 + c] = ax[li][c];

        // ---- Hy_n: stream E rows i0-2..i0+6, cols j0..j0+7 (2x float4) ----
        float ay[4][4];
        #pragma unroll
        for (int li = 0; li < 4; ++li) {
            const float* yb = Hy + (i0+li)*1022 + j0;
            float2 v0 = *reinterpret_cast<const float2*>(yb);
            float2 v1 = *reinterpret_cast<const float2*>(yb + 2);
            ay[li][0]=v0.x; ay[li][1]=v0.y; ay[li][2]=v1.x; ay[li][3]=v1.y;
        }

        #pragma unroll
        for (int t = 0; t < 9; ++t) {
            const float* eb = E + (i0 - 2 + t)*1024 + j0;
            float4 e0 = *reinterpret_cast<const float4*>(eb);
            float4 e1 = *reinterpret_cast<const float4*>(eb + 4);
            float e[8] = { e0.x,e0.y,e0.z,e0.w, e1.x,e1.y,e1.z,e1.w };
            #pragma unroll
            for (int li = 0; li < 4; ++li) {
                const int o = t - li;          // combined 6-tap vertical, col j+1
                if (o >= 0 && o < 6) {
                    #pragma unroll
                    for (int c = 0; c < 4; ++c)
                        ay[li][c] = fmaf(FX6[o], e[c+1], ay[li][c]);
                }
                const int a = t - 1 - li;      // conv(E, f^T), added
                if (a >= 0 && a < 4) {
                    #pragma unroll
                    for (int bb = 0; bb < 3; ++bb)
                        #pragma unroll
                        for (int c = 0; c < 4; ++c)
                            ay[li][c] = fmaf(fl05[bb*4 + a], e[c+bb], ay[li][c]);
                }
            }
        }
        #pragma unroll
        for (int li = 0; li < 4; ++li) {
            float* yo = Hyout + (i0+li)*1022 + j0;
            *reinterpret_cast<float2*>(yo)     = make_float2(ay[li][0], ay[li][1]);
            *reinterpret_cast<float2*>(yo + 2) = make_float2(ay[li][2], ay[li][3]);
        }
    } else {
        #pragma unroll
        for (int li = 0; li < 4; ++li) {
            const int i = i0 + li;
            for (int c = 0; c < 4; ++c) {
                const int j = j0 + c;
                if (i < 1022 && j < 1023) Hxout[i*1023 + j] = hx_pt_slow(E, Hx, F, i, j);
                if (i < 1023 && j < 1022) Hyout[i*1022 + j] = hy_pt_slow(E, Hy, F, i, j);
            }
        }
    }
}

// ---------------------------------------------------------------------------
// Launch: 4 passes; intermediates (E_n, Hx_n, Hy_n) live directly in d_out.
// ---------------------------------------------------------------------------
extern "C" void kernel_launch(void* const* d_in, const int* in_sizes, int n_in,
                              void* d_out, int out_size)
{
    const float* E  = (const float*)d_in[0];   // (8,1024,1024,1)
    const float* Hx = (const float*)d_in[1];   // (8,1022,1023,1)
    const float* Hy = (const float*)d_in[2];   // (8,1023,1022,1)
    const float* F  = (const float*)d_in[3];   // (3,4,1,1)

    float* out   = (float*)d_out;
    const int B  = 8;
    float* outE  = out;                                   // 8 * 2048*1024
    float* outHx = outE  + (size_t)B * 2048 * 1024;       // 8 * 2044*1023
    float* outHy = outHx + (size_t)B * 2044 * 1023;       // 8 * 2046*1022

    const int Es   = 1024*1024, Hxs  = 1022*1023, Hys  = 1023*1022;
    const int Eos  = 2048*1024, Hxos = 2044*1023, Hyos = 2046*1022;

    dim3 blk(32, 8, 1);
    dim3 grd(8, 32, B);   // thread tile 4x4; block tile 32 rows x 128 cols

    // Step 1
    amper_kernel<<<grd, blk>>>(E, Es, Hx, Hxs, Hy, Hys, F, outE, Eos);
    faraday_kernel<<<grd, blk>>>(outE, Eos, Hx, Hxs, Hy, Hys, F,
                                 outHx, Hxos, outHy, Hyos);
    // Step 2 (reads step-1 results from d_out)
    amper_kernel<<<grd, blk>>>(outE, Eos, outHx, Hxos, outHy, Hyos, F,
                               outE + 1024*1024, Eos);
    faraday_kernel<<<grd, blk>>>(outE + 1024*1024, Eos, outHx, Hxos, outHy, Hyos, F,
                                 outHx + 1022*1023, Hxos, outHy + 1023*1022, Hyos);
}

// round 17
// speedup vs baseline: 1.7434x; 1.0823x over previous
#include <cuda_runtime.h>

// FDTD 2-step update (Ampere + Faraday, 3rd-order one-sided boundary stencils)
// B=8, E:1024x1024, Hx:1022x1023, Hy:1023x1022.
// Outputs concat axis 1: E:(8,2048,1024)  Hx:(8,2044,1023)  Hy:(8,2046,1022)
// DT/DX = DT/(Z*DY) = 0.5 ; cf = [-11/6, 3, -3/2, 1/3]

#define CF0 (-11.0f/6.0f)
#define CF1 ( 3.0f)
#define CF2 (-1.5f)
#define CF3 ( 1.0f/3.0f)

#define W8_INIT  { -0.5f*CF3, -0.5f*CF2, -0.5f*CF1, -0.5f*CF0, 0.5f*CF0, 0.5f*CF1, 0.5f*CF2, 0.5f*CF3 }
#define HW8_INIT {  0.5f*CF3,  0.5f*CF2,  0.5f*CF1,  0.5f*CF0,-0.5f*CF0,-0.5f*CF1,-0.5f*CF2,-0.5f*CF3 }
#define FX6_INIT { -0.5f*CF3, -0.5f*CF2, 0.5f*(CF0-CF1), 0.5f*(CF1-CF0), 0.5f*CF2, 0.5f*CF3 }

// ===========================================================================
// Per-point slow-path (boundary) functions — identical math to passing code.
// ===========================================================================
__device__ __noinline__ float amper_pt_slow(
    const float* __restrict__ E, const float* __restrict__ Hx,
    const float* __restrict__ Hy, const float* __restrict__ F, int i, int j)
{
    float fl[12];
    #pragma unroll
    for (int k = 0; k < 12; k++) fl[k] = __ldg(F + k);

    float s = __ldg(E + i*1024 + j);
    if (i >= 2 && i <= 1021 && j >= 2 && j <= 1021) {
        float a1 = 0.f;
        #pragma unroll
        for (int a = 0; a < 4; a++)
            #pragma unroll
            for (int b = 0; b < 3; b++)
                a1 = fmaf(__ldg(Hy + (i-2+a)*1022 + (j-2+b)), fl[b*4+a], a1);
        float a2 = 0.f;
        #pragma unroll
        for (int a = 0; a < 3; a++)
            #pragma unroll
            for (int b = 0; b < 4; b++)
                a2 = fmaf(__ldg(Hx + (i-2+a)*1023 + (j-2+b)), fl[a*4+b], a2);
        s += 0.5f * (a1 - a2);
    }
    if (i <= 1019 && j >= 1 && j <= 1022) {
        const float* p = Hy + i*1022 + (j-1);
        s += 0.5f*(CF0*__ldg(p) + CF1*__ldg(p+1022) + CF2*__ldg(p+2044) + CF3*__ldg(p+3066));
    }
    if (i >= 4 && j >= 1 && j <= 1022) {
        const float* p = Hy + (i-4)*1022 + (j-1);
        s -= 0.5f*(CF3*__ldg(p) + CF2*__ldg(p+1022) + CF1*__ldg(p+2044) + CF0*__ldg(p+3066));
    }
    if (i >= 1 && i <= 1022 && j <= 1019) {
        const float* p = Hx + (i-1)*1023 + j;
        s -= 0.5f*(CF0*__ldg(p) + CF1*__ldg(p+1) + CF2*__ldg(p+2) + CF3*__ldg(p+3));
    }
    if (i >= 1 && i <= 1022 && j >= 4) {
        const float* p = Hx + (i-1)*1023 + (j-4);
        s += 0.5f*(CF3*__ldg(p) + CF2*__ldg(p+1) + CF1*__ldg(p+2) + CF0*__ldg(p+3));
    }
    return s;
}

__device__ __noinline__ float hx_pt_slow(
    const float* __restrict__ E, const float* __restrict__ Hx,
    const float* __restrict__ F, int i, int j)
{
    float fl[12];
    #pragma unroll
    for (int k = 0; k < 12; k++) fl[k] = __ldg(F + k);

    float s3 = 0.f;
    if (j >= 1 && j <= 1021) {
        float a = 0.f;
        #pragma unroll
        for (int a2 = 0; a2 < 3; a2++)
            #pragma unroll
            for (int b = 0; b < 4; b++)
                a = fmaf(__ldg(E + (i+a2)*1024 + (j-1+b)), fl[a2*4+b], a);
        s3 += 0.5f * a;
    }
    if (j <= 1020) {
        const float* p = E + (i+1)*1024 + j;
        s3 += 0.5f*(CF0*__ldg(p) + CF1*__ldg(p+1) + CF2*__ldg(p+2) + CF3*__ldg(p+3));
    }
    if (j >= 2) {
        const float* p = E + (i+1)*1024 + (j-2);
        s3 -= 0.5f*(CF3*__ldg(p) + CF2*__ldg(p+1) + CF1*__ldg(p+2) + CF0*__ldg(p+3));
    }
    return __ldg(Hx + i*1023 + j) - s3;
}

__device__ __noinline__ float hy_pt_slow(
    const float* __restrict__ E, const float* __restrict__ Hy,
    const float* __restrict__ F, int i, int j)
{
    float fl[12];
    #pragma unroll
    for (int k = 0; k < 12; k++) fl[k] = __ldg(F + k);

    float s4 = 0.f;
    if (i >= 1 && i <= 1021) {
        float a = 0.f;
        #pragma unroll
        for (int a2 = 0; a2 < 4; a2++)
            #pragma unroll
            for (int b = 0; b < 3; b++)
                a = fmaf(__ldg(E + (i-1+a2)*1024 + (j+b)), fl[b*4+a2], a);
        s4 += 0.5f * a;
    }
    if (i <= 1020) {
        const float* p = E + i*1024 + (j+1);
        s4 += 0.5f*(CF0*__ldg(p) + CF1*__ldg(p+1024) + CF2*__ldg(p+2048) + CF3*__ldg(p+3072));
    }
    if (i >= 2) {
        const float* p = E + (i-2)*1024 + (j+1);
        s4 -= 0.5f*(CF3*__ldg(p) + CF2*__ldg(p+1024) + CF1*__ldg(p+2048) + CF0*__ldg(p+3072));
    }
    return __ldg(Hy + i*1022 + j) + s4;
}

// ===========================================================================
// Ampere kernel: 4x4 tile, register streaming, folded conv middle row/col.
//   W8c[o]  = W8[o]  + fl05[o+2]  (o in [2,5])  — conv(Hy,f^T) col j-1 folded
//   HW8c[o] = HW8[o] - fl05[o+2]  (o in [2,5])  — conv(Hx,f) row i-1 folded
// Remaining conv loops: Hy over bb in {0,2}; Hx over a in {0,2}.
// ===========================================================================
__global__ __launch_bounds__(256, 4)
void amper_kernel(const float* __restrict__ E,  int Es,
                  const float* __restrict__ Hx, int Hxs,
                  const float* __restrict__ Hy, int Hys,
                  const float* __restrict__ F,
                  float* __restrict__ Eout, int Eos)
{
    const int b = blockIdx.z;
    E    += (size_t)b * Es;
    Hx   += (size_t)b * Hxs;
    Hy   += (size_t)b * Hys;
    Eout += (size_t)b * Eos;

    const int j0 = (blockIdx.x * 32 + threadIdx.x) * 4;   // 0..1020
    const int i0 = (blockIdx.y * 8  + threadIdx.y) * 4;   // 0..1020

    if (i0 >= 4 && i0 <= 1016 && j0 >= 4 && j0 <= 1016) {
        float fl05[12];
        #pragma unroll
        for (int k = 0; k < 12; k++) fl05[k] = 0.5f * __ldg(F + k);

        const float W8[8]  = W8_INIT;
        const float HW8[8] = HW8_INIT;
        float W8c[8], HW8c[8];
        #pragma unroll
        for (int o = 0; o < 8; ++o) { W8c[o] = W8[o]; HW8c[o] = HW8[o]; }
        #pragma unroll
        for (int o = 2; o < 6; ++o) { W8c[o] += fl05[o+2]; HW8c[o] -= fl05[o+2]; }

        float acc[4][4];
        #pragma unroll
        for (int li = 0; li < 4; ++li) {
            float4 e = *reinterpret_cast<const float4*>(E + (i0+li)*1024 + j0);
            acc[li][0]=e.x; acc[li][1]=e.y; acc[li][2]=e.z; acc[li][3]=e.w;
        }

        // ---- Hy phase: stream 11 rows (i0-4 .. i0+6), cols j0-2..j0+3 ----
        #pragma unroll
        for (int t = 0; t < 11; ++t) {
            const float* hb = Hy + (i0 - 4 + t)*1022 + (j0 - 2);
            float2 v0 = *reinterpret_cast<const float2*>(hb);
            float2 v1 = *reinterpret_cast<const float2*>(hb + 2);
            float2 v2 = *reinterpret_cast<const float2*>(hb + 4);
            float h[6] = { v0.x, v0.y, v1.x, v1.y, v2.x, v2.y };
            #pragma unroll
            for (int li = 0; li < 4; ++li) {
                const int o = t - li;          // vertical 8-tap + folded conv col, at h[c+1]
                if (o >= 0 && o < 8) {
                    #pragma unroll
                    for (int c = 0; c < 4; ++c)
                        acc[li][c] = fmaf(W8c[o], h[c+1], acc[li][c]);
                }
                const int a = t - 2 - li;      // conv(Hy,f^T) remaining cols bb in {0,2}
                if (a >= 0 && a < 4) {
                    #pragma unroll
                    for (int c = 0; c < 4; ++c) {
                        acc[li][c] = fmaf(fl05[a],     h[c],   acc[li][c]);   // bb=0
                        acc[li][c] = fmaf(fl05[8 + a], h[c+2], acc[li][c]);   // bb=2
                    }
                }
            }
        }

        // ---- Hx phase: stream 6 rows (i0-2 .. i0+3), cols j0-4..j0+6 ----
        #pragma unroll
        for (int t = 0; t < 6; ++t) {
            const float* xb = Hx + (i0 - 2 + t)*1023 + (j0 - 4);
            float x[11];
            // t=0 and t=5 only feed the conv remainder (needs x[2..8])
            const int klo = (t == 0 || t == 5) ? 2 : 0;
            const int khi = (t == 0 || t == 5) ? 9 : 11;
            #pragma unroll
            for (int k = 0; k < 11; ++k)
                if (k >= klo && k < khi) x[k] = __ldg(xb + k);
            {
                const int li = t - 1;          // horizontal 8-tap + folded conv row
                if (li >= 0 && li < 4) {
                    #pragma unroll
                    for (int c = 0; c < 4; ++c)
                        #pragma unroll
                        for (int o = 0; o < 8; ++o)
                            acc[li][c] = fmaf(HW8c[o], x[c+o], acc[li][c]);
                }
            }
            #pragma unroll
            for (int li = 0; li < 4; ++li) {
                const int a = t - li;          // conv(Hx,f) remaining rows a in {0,2}
                if (a == 0 || a == 2) {
                    #pragma unroll
                    for (int bb = 0; bb < 4; ++bb)
                        #pragma unroll
                        for (int c = 0; c < 4; ++c)
                            acc[li][c] = fmaf(-fl05[a*4 + bb], x[c+2+bb], acc[li][c]);
                }
            }
        }

        #pragma unroll
        for (int li = 0; li < 4; ++li)
            *reinterpret_cast<float4*>(Eout + (i0+li)*1024 + j0) =
                make_float4(acc[li][0], acc[li][1], acc[li][2], acc[li][3]);
    } else {
        #pragma unroll
        for (int li = 0; li < 4; ++li)
            for (int c = 0; c < 4; ++c)
                Eout[(i0+li)*1024 + j0 + c] = amper_pt_slow(E, Hx, Hy, F, i0+li, j0+c);
    }
}

// ===========================================================================
// Faraday kernel: 2x4 tile, ONE merged E stream serves both Hx_n and Hy_n.
// Stream rows i0-2..i0+4 (7 rows), cols j0-4..j0+7 (3 float4).
//   C6[o] = FX6[o] + fl05[o+3] (o in [1,4]) — shared fold for both fields.
// Remaining conv loops: Hy over bb in {0,2}; Hx over a in {0,2}.
// ===========================================================================
__global__ __launch_bounds__(256, 5)
void faraday_kernel(const float* __restrict__ E,  int Es,
                    const float* __restrict__ Hx, int Hxs,
                    const float* __restrict__ Hy, int Hys,
                    const float* __restrict__ F,
                    float* __restrict__ Hxout, int Hxos,
                    float* __restrict__ Hyout, int Hyos)
{
    const int b = blockIdx.z;
    E     += (size_t)b * Es;
    Hx    += (size_t)b * Hxs;
    Hy    += (size_t)b * Hys;
    Hxout += (size_t)b * Hxos;
    Hyout += (size_t)b * Hyos;

    const int j0 = (blockIdx.x * 32 + threadIdx.x) * 4;   // 0..1020
    const int i0 = (blockIdx.y * 8  + threadIdx.y) * 2;   // 0..1022

    if (i0 >= 2 && i0 <= 1018 && j0 >= 4 && j0 <= 1016) {
        float fl05[12];
        #pragma unroll
        for (int k = 0; k < 12; k++) fl05[k] = 0.5f * __ldg(F + k);

        const float FX6[6] = FX6_INIT;
        float C6[6];
        #pragma unroll
        for (int o = 0; o < 6; ++o) C6[o] = FX6[o];
        #pragma unroll
        for (int o = 1; o < 5; ++o) C6[o] += fl05[o+3];

        float ax[2][4], ay[2][4];
        #pragma unroll
        for (int li = 0; li < 2; ++li) {
            #pragma unroll
            for (int c = 0; c < 4; ++c)
                ax[li][c] = __ldg(Hx + (i0+li)*1023 + j0 + c);
            const float* yb = Hy + (i0+li)*1022 + j0;
            float2 v0 = *reinterpret_cast<const float2*>(yb);
            float2 v1 = *reinterpret_cast<const float2*>(yb + 2);
            ay[li][0]=v0.x; ay[li][1]=v0.y; ay[li][2]=v1.x; ay[li][3]=v1.y;
        }

        #pragma unroll
        for (int t = 0; t < 7; ++t) {
            const float* eb = E + (i0 - 2 + t)*1024 + (j0 - 4);
            float4 e0 = *reinterpret_cast<const float4*>(eb);
            float4 e1 = *reinterpret_cast<const float4*>(eb + 4);
            float4 e2 = *reinterpret_cast<const float4*>(eb + 8);
            float e[12] = { e0.x,e0.y,e0.z,e0.w, e1.x,e1.y,e1.z,e1.w, e2.x,e2.y,e2.z,e2.w };

            #pragma unroll
            for (int li = 0; li < 2; ++li) {
                // Hy: combined 6-tap (+folded conv col j+1), at e[c+5]
                const int o = t - li;
                if (o >= 0 && o < 6) {
                    #pragma unroll
                    for (int c = 0; c < 4; ++c)
                        ay[li][c] = fmaf(C6[o], e[c+5], ay[li][c]);
                }
                // Hy: conv(E,f^T) remaining cols bb in {0,2}, rows i-1..i+2
                const int a = t - 1 - li;
                if (a >= 0 && a < 4) {
                    #pragma unroll
                    for (int c = 0; c < 4; ++c) {
                        ay[li][c] = fmaf(fl05[a],     e[c+4], ay[li][c]);   // bb=0
                        ay[li][c] = fmaf(fl05[8 + a], e[c+6], ay[li][c]);   // bb=2
                    }
                }
                // Hx: combined 6-tap (+folded conv row i+1), row i+1 -> t = li+3
                if (t - li == 3) {
                    #pragma unroll
                    for (int c = 0; c < 4; ++c)
                        #pragma unroll
                        for (int o2 = 0; o2 < 6; ++o2)
                            ax[li][c] = fmaf(-C6[o2], e[c+2+o2], ax[li][c]);
                }
                // Hx: conv(E,f) remaining rows a in {0,2}, cols j-1..j+2
                const int a2 = t - 2 - li;
                if (a2 == 0 || a2 == 2) {
                    #pragma unroll
                    for (int bb = 0; bb < 4; ++bb)
                        #pragma unroll
                        for (int c = 0; c < 4; ++c)
                            ax[li][c] = fmaf(-fl05[a2*4 + bb], e[c+3+bb], ax[li][c]);
                }
            }
        }

        #pragma unroll
        for (int li = 0; li < 2; ++li) {
            #pragma unroll
            for (int c = 0; c < 4; ++c)
                Hxout[(i0+li)*1023 + j0 + c] = ax[li][c];
            float* yo = Hyout + (i0+li)*1022 + j0;
            *reinterpret_cast<float2*>(yo)     = make_float2(ay[li][0], ay[li][1]);
            *reinterpret_cast<float2*>(yo + 2) = make_float2(ay[li][2], ay[li][3]);
        }
    } else {
        #pragma unroll
        for (int li = 0; li < 2; ++li) {
            const int i = i0 + li;
            for (int c = 0; c < 4; ++c) {
                const int j = j0 + c;
                if (i < 1022 && j < 1023) Hxout[i*1023 + j] = hx_pt_slow(E, Hx, F, i, j);
                if (i < 1023 && j < 1022) Hyout[i*1022 + j] = hy_pt_slow(E, Hy, F, i, j);
            }
        }
    }
}

// ---------------------------------------------------------------------------
// Launch: 4 passes; intermediates (E_n, Hx_n, Hy_n) live directly in d_out.
// ---------------------------------------------------------------------------
extern "C" void kernel_launch(void* const* d_in, const int* in_sizes, int n_in,
                              void* d_out, int out_size)
{
    const float* E  = (const float*)d_in[0];   // (8,1024,1024,1)
    const float* Hx = (const float*)d_in[1];   // (8,1022,1023,1)
    const float* Hy = (const float*)d_in[2];   // (8,1023,1022,1)
    const float* F  = (const float*)d_in[3];   // (3,4,1,1)

    float* out   = (float*)d_out;
    const int B  = 8;
    float* outE  = out;                                   // 8 * 2048*1024
    float* outHx = outE  + (size_t)B * 2048 * 1024;       // 8 * 2044*1023
    float* outHy = outHx + (size_t)B * 2044 * 1023;       // 8 * 2046*1022

    const int Es   = 1024*1024, Hxs  = 1022*1023, Hys  = 1023*1022;
    const int Eos  = 2048*1024, Hxos = 2044*1023, Hyos = 2046*1022;

    dim3 blkA(32, 8, 1);
    dim3 grdA(8, 32, B);    // amper: thread 4x4; block 32 rows x 128 cols
    dim3 blkF(32, 8, 1);
    dim3 grdF(8, 64, B);    // faraday: thread 2x4; block 16 rows x 128 cols

    // Step 1
    amper_kernel<<<grdA, blkA>>>(E, Es, Hx, Hxs, Hy, Hys, F, outE, Eos);
    faraday_kernel<<<grdF, blkF>>>(outE, Eos, Hx, Hxs, Hy, Hys, F,
                                   outHx, Hxos, outHy, Hyos);
    // Step 2 (reads step-1 results from d_out)
    amper_kernel<<<grdA, blkA>>>(outE, Eos, outHx, Hxos, outHy, Hyos, F,
                                 outE + 1024*1024, Eos);
    faraday_kernel<<<grdF, blkF>>>(outE + 1024*1024, Eos, outHx, Hxos, outHy, Hyos, F,
                                   outHx + 1022*1023, Hxos, outHy + 1023*1022, Hyos);
}